// round 12
// baseline (speedup 1.0000x reference)
#include <cuda_runtime.h>
#include <cuda_bf16.h>
#include <math.h>
#include <stdint.h>

#define BB 256
#define SS 128
#define EE 512
#define HH 1024
#define VV 128
#define CC 18

// ---------------- device scratch (no cudaMalloc allowed) ----------------
__device__ float          g_T[VV * HH];     // T[v][h] = W_ih.emb[v] + b_ih + b_hh
__device__ __nv_bfloat16  g_ah[BB * HH];    // h split hi (bf16)
__device__ __nv_bfloat16  g_al[BB * HH];    // h split lo (bf16)
__device__ __nv_bfloat16  g_wh[HH * HH];    // W_hh split hi
__device__ __nv_bfloat16  g_wl[HH * HH];    // W_hh split lo
__device__ float          g_last[BB * HH];
__device__ float          g_mlp1[BB * HH];
__device__ int            g_xin[BB * SS];
__device__ int            g_len[BB];
__device__ int            g_cnt[4];
__device__ volatile int   g_sense[4];

// ---------------------------------------------------------------------------
// Preprocessing
// ---------------------------------------------------------------------------
__global__ void __launch_bounds__(256) convert_inputs(const void* xin_raw,
                                                      const void* xlen_raw) {
    long long probe = ((const long long*)xlen_raw)[0];
    bool is64 = (probe >= 1 && probe <= SS);
    int i = blockIdx.x * blockDim.x + threadIdx.x;
    if (i < BB * SS) {
        g_xin[i] = is64 ? (int)((const long long*)xin_raw)[i]
                        : ((const int*)xin_raw)[i];
    }
    if (i < BB) {
        g_len[i] = is64 ? (int)((const long long*)xlen_raw)[i]
                        : ((const int*)xlen_raw)[i];
    }
}

__global__ void __launch_bounds__(256) split_whh(const float* __restrict__ W) {
    int i = blockIdx.x * blockDim.x + threadIdx.x;
    if (i < HH * HH) {
        float w = W[i];
        __nv_bfloat16 hi = __float2bfloat16_rn(w);
        float lo = w - __bfloat162float(hi);
        g_wh[i] = hi;
        g_wl[i] = __float2bfloat16_rn(lo);
    }
}

// ---------------------------------------------------------------------------
// Generic tiled GEMM (aux)
// ---------------------------------------------------------------------------
__global__ void __launch_bounds__(256) gemm_bias_act(
    const float* __restrict__ A, const float* __restrict__ Bm,
    const float* __restrict__ bias, const float* __restrict__ bias2,
    float* __restrict__ Cout, int M, int N, int K, int act)
{
    __shared__ float As[32][33];
    __shared__ float Bs[32][65];

    const int tid = threadIdx.x;
    const int tx = tid & 15;
    const int ty = tid >> 4;
    const int m0 = blockIdx.y * 32;
    const int n0 = blockIdx.x * 64;
    const int ka = tid & 31;
    const int ra = tid >> 5;

    float acc[2][4] = {};

    for (int k0 = 0; k0 < K; k0 += 32) {
        #pragma unroll
        for (int r = 0; r < 4; r++)
            As[ka][ra + r * 8] = A[(size_t)(m0 + ra + r * 8) * K + k0 + ka];
        #pragma unroll
        for (int r = 0; r < 8; r++) {
            int n = ra + r * 8;
            float v = 0.0f;
            if (n0 + n < N) v = Bm[(size_t)(n0 + n) * K + k0 + ka];
            Bs[ka][n] = v;
        }
        __syncthreads();
        #pragma unroll
        for (int kk = 0; kk < 32; kk++) {
            float a[2], b[4];
            #pragma unroll
            for (int i = 0; i < 2; i++) a[i] = As[kk][ty * 2 + i];
            #pragma unroll
            for (int j = 0; j < 4; j++) b[j] = Bs[kk][tx * 4 + j];
            #pragma unroll
            for (int i = 0; i < 2; i++)
                #pragma unroll
                for (int j = 0; j < 4; j++)
                    acc[i][j] = fmaf(a[i], b[j], acc[i][j]);
        }
        __syncthreads();
    }

    #pragma unroll
    for (int i = 0; i < 2; i++) {
        int m = m0 + ty * 2 + i;
        if (m >= M) continue;
        #pragma unroll
        for (int j = 0; j < 4; j++) {
            int n = n0 + tx * 4 + j;
            if (n >= N) continue;
            float z = acc[i][j] + bias[n];
            if (bias2) z += bias2[n];
            if (act == 1) z = fmaxf(z, 0.0f);
            Cout[(size_t)m * N + n] = z;
        }
    }
}

// ---------------------------------------------------------------------------
// Persistent RNN on tensor cores via mma.sync m16n8k16 bf16 (3-term split).
// 128 CTAs = 4 m-groups (64 rows) x 32 n-blocks (32 cols), 256 threads.
// W_hh (hi+lo) resident in smem k-major [n][kpair-u32]; A streamed per step
// in 8 chunks of k=128 (double-buffered smem, register prefetch).
// Warps: 4 m x 2 n, warp tile m16 x n32 (two n8 tiles per 16-col span... 4 n8
// tiles total: cols 16*wn + {0,8} only => n16 per warp? No: wn in {0,1} covers
// cols 0..15 / 16..31 with 2 n8 tiles each).
// ---------------------------------------------------------------------------
#define WS 516                       // u32 stride per W row (512 + 4 pad)
#define AS 68                        // u32 stride per A row (64 + 4 pad)
#define WH_OFF 0
#define WL_OFF (32 * WS)             // 16512
#define AB_OFF (2 * 32 * WS)         // 33024
#define A_CH   (64 * AS)             // 4352 u32 per chunk
#define AB_STEP (2 * A_CH)           // hi+lo per buffer
#define SMEM_U32 (AB_OFF + 2 * AB_STEP)
#define SMEM_BYTES (SMEM_U32 * 4)    // 201728

#define MMA(c, A0, A1, A2, A3, B0, B1) \
    asm volatile( \
        "mma.sync.aligned.m16n8k16.row.col.f32.bf16.bf16.f32 " \
        "{%0,%1,%2,%3}, {%4,%5,%6,%7}, {%8,%9}, {%0,%1,%2,%3};" \
        : "+f"((c)[0]), "+f"((c)[1]), "+f"((c)[2]), "+f"((c)[3]) \
        : "r"(A0), "r"(A1), "r"(A2), "r"(A3), "r"(B0), "r"(B1))

__global__ void __launch_bounds__(256, 1) rnn_mma()
{
    extern __shared__ uint32_t sm[];

    const int tid = threadIdx.x;
    const int wid = tid >> 5;
    const int lid = tid & 31;
    const int gi = blockIdx.x >> 5;        // m-group 0..3
    const int gj = blockIdx.x & 31;        // n-block 0..31
    const int m0 = gi * 64;
    const int n0 = gj * 32;

    const int g = lid >> 2;                // 0..7
    const int q = lid & 3;                 // 0..3
    const int wm = wid & 3;                // m-warp 0..3
    const int wn = wid >> 2;               // n-warp 0..1
    const int mwl = 16 * wm;               // local row base
    const int nwl = 16 * wn;               // local col base

    // ---- load resident W (hi+lo) k-major into smem ----
    {
        const uint4* gwh = (const uint4*)g_wh;
        const uint4* gwl = (const uint4*)g_wl;
        for (int idx = tid; idx < 32 * 128; idx += 256) {
            int row = idx >> 7;            // 0..31
            int slot = idx & 127;          // uint4 slot (4 kpairs)
            uint4 vh = gwh[(size_t)(n0 + row) * 128 + slot];
            uint4 vl = gwl[(size_t)(n0 + row) * 128 + slot];
            *(uint4*)(sm + WH_OFF + row * WS + slot * 4) = vh;
            *(uint4*)(sm + WL_OFF + row * WS + slot * 4) = vl;
        }
    }
    __syncthreads();

    // per-lane W bases (u32 index)
    const int wb0h = WH_OFF + (nwl + g) * WS + q;       // n8-tile 0
    const int wb1h = wb0h + 8 * WS;                     // n8-tile 1
    const int wb0l = wb0h + (WL_OFF - WH_OFF);
    const int wb1l = wb1h + (WL_OFF - WH_OFF);
    // per-lane A frag bases (relative to chunk buffer)
    const int ar0 = (mwl + g) * AS + q;
    const int ar1 = ar0 + 8 * AS;

    // staging coords: row = (tid>>4)+16j, slot = tid&15 (uint4)
    const int st_r = tid >> 4;
    const int st_s = tid & 15;

    // epilogue row info
    const int me0 = m0 + mwl + g;
    const int me1 = me0 + 8;
    const int len0 = g_len[me0];
    const int len1 = g_len[me1];
    const int colb = n0 + nwl + 2 * q;     // tile0 col base (even)

    const uint4* gah = (const uint4*)g_ah;
    const uint4* gal = (const uint4*)g_al;

    for (int t = 0; t < SS; t++) {
        float acc0[4] = {0.f, 0.f, 0.f, 0.f};   // n8 tile 0
        float acc1[4] = {0.f, 0.f, 0.f, 0.f};   // n8 tile 1

        if (t > 0) {
            uint4 pfh[4], pfl[4];
            // prefetch + store chunk 0
            #pragma unroll
            for (int j = 0; j < 4; j++) {
                int row = st_r + 16 * j;
                size_t gidx = (size_t)(m0 + row) * 128 + st_s;
                pfh[j] = __ldcg(gah + gidx);
                pfl[j] = __ldcg(gal + gidx);
            }
            #pragma unroll
            for (int j = 0; j < 4; j++) {
                int row = st_r + 16 * j;
                *(uint4*)(sm + AB_OFF + row * AS + st_s * 4) = pfh[j];
                *(uint4*)(sm + AB_OFF + A_CH + row * AS + st_s * 4) = pfl[j];
            }
            __syncthreads();

            for (int c = 0; c < 8; c++) {
                // prefetch chunk c+1
                if (c + 1 < 8) {
                    #pragma unroll
                    for (int j = 0; j < 4; j++) {
                        int row = st_r + 16 * j;
                        size_t gidx = (size_t)(m0 + row) * 128 + (c + 1) * 16 + st_s;
                        pfh[j] = __ldcg(gah + gidx);
                        pfl[j] = __ldcg(gal + gidx);
                    }
                }

                // compute chunk c (8 k16-steps)
                const int ab = AB_OFF + (c & 1) * AB_STEP;
                #pragma unroll
                for (int ks = 0; ks < 8; ks++) {
                    const int ka = ks * 8;                // A kpair offset
                    const int kw = c * 64 + ks * 8;       // W kpair offset
                    uint32_t ah0 = sm[ab + ar0 + ka];
                    uint32_t ah1 = sm[ab + ar1 + ka];
                    uint32_t ah2 = sm[ab + ar0 + ka + 4];
                    uint32_t ah3 = sm[ab + ar1 + ka + 4];
                    uint32_t bh00 = sm[wb0h + kw];
                    uint32_t bh01 = sm[wb0h + kw + 4];
                    uint32_t bh10 = sm[wb1h + kw];
                    uint32_t bh11 = sm[wb1h + kw + 4];
                    MMA(acc0, ah0, ah1, ah2, ah3, bh00, bh01);
                    MMA(acc1, ah0, ah1, ah2, ah3, bh10, bh11);
                    uint32_t bl00 = sm[wb0l + kw];
                    uint32_t bl01 = sm[wb0l + kw + 4];
                    uint32_t bl10 = sm[wb1l + kw];
                    uint32_t bl11 = sm[wb1l + kw + 4];
                    MMA(acc0, ah0, ah1, ah2, ah3, bl00, bl01);
                    MMA(acc1, ah0, ah1, ah2, ah3, bl10, bl11);
                    uint32_t al0 = sm[ab + A_CH + ar0 + ka];
                    uint32_t al1 = sm[ab + A_CH + ar1 + ka];
                    uint32_t al2 = sm[ab + A_CH + ar0 + ka + 4];
                    uint32_t al3 = sm[ab + A_CH + ar1 + ka + 4];
                    MMA(acc0, al0, al1, al2, al3, bh00, bh01);
                    MMA(acc1, al0, al1, al2, al3, bh10, bh11);
                }

                // store prefetched chunk
                if (c + 1 < 8) {
                    const int db = AB_OFF + ((c + 1) & 1) * AB_STEP;
                    #pragma unroll
                    for (int j = 0; j < 4; j++) {
                        int row = st_r + 16 * j;
                        *(uint4*)(sm + db + row * AS + st_s * 4) = pfh[j];
                        *(uint4*)(sm + db + A_CH + row * AS + st_s * 4) = pfl[j];
                    }
                }
                __syncthreads();
            }
        }

        // ---- epilogue: 2 rows x 4 cols per thread ----
        #pragma unroll
        for (int r = 0; r < 2; r++) {
            int m = r ? me1 : me0;
            int xi = g_xin[m * SS + t];
            float2 tv0 = *(const float2*)(g_T + (size_t)xi * HH + colb);
            float2 tv1 = *(const float2*)(g_T + (size_t)xi * HH + colb + 8);
            float v0 = tv0.x, v1 = tv0.y, v2 = tv1.x, v3 = tv1.y;
            if (t > 0) {
                v0 += acc0[2 * r];  v1 += acc0[2 * r + 1];
                v2 += acc1[2 * r];  v3 += acc1[2 * r + 1];
            }
            v0 = tanhf(v0); v1 = tanhf(v1); v2 = tanhf(v2); v3 = tanhf(v3);

            __nv_bfloat16 h0 = __float2bfloat16_rn(v0);
            __nv_bfloat16 h1 = __float2bfloat16_rn(v1);
            __nv_bfloat16 h2 = __float2bfloat16_rn(v2);
            __nv_bfloat16 h3 = __float2bfloat16_rn(v3);
            __nv_bfloat16 l0 = __float2bfloat16_rn(v0 - __bfloat162float(h0));
            __nv_bfloat16 l1 = __float2bfloat16_rn(v1 - __bfloat162float(h1));
            __nv_bfloat16 l2 = __float2bfloat16_rn(v2 - __bfloat162float(h2));
            __nv_bfloat16 l3 = __float2bfloat16_rn(v3 - __bfloat162float(h3));

            uint32_t* ph = (uint32_t*)g_ah + (size_t)m * (HH / 2) + colb / 2;
            uint32_t* pl = (uint32_t*)g_al + (size_t)m * (HH / 2) + colb / 2;
            ph[0] = (uint32_t)__bfloat16_as_ushort(h0)
                  | ((uint32_t)__bfloat16_as_ushort(h1) << 16);
            ph[4] = (uint32_t)__bfloat16_as_ushort(h2)
                  | ((uint32_t)__bfloat16_as_ushort(h3) << 16);
            pl[0] = (uint32_t)__bfloat16_as_ushort(l0)
                  | ((uint32_t)__bfloat16_as_ushort(l1) << 16);
            pl[4] = (uint32_t)__bfloat16_as_ushort(l2)
                  | ((uint32_t)__bfloat16_as_ushort(l3) << 16);

            if (t == (r ? len1 : len0) - 1) {
                float2* dl = (float2*)(g_last + (size_t)m * HH + colb);
                dl[0] = make_float2(v0, v1);
                dl[4] = make_float2(v2, v3);
            }
        }

        // ---- per-m-group barrier (32 CTAs), replay-safe ----
        __syncthreads();
        if (tid == 0) {
            __threadfence();
            int target = (t + 1) & 127;
            int arrived = atomicAdd(&g_cnt[gi], 1);
            if (arrived == 31) {
                g_cnt[gi] = 0;
                __threadfence();
                g_sense[gi] = target;
            } else {
                while (g_sense[gi] != target) { }
                __threadfence();
            }
        }
        __syncthreads();
    }
}

extern "C" void kernel_launch(void* const* d_in, const int* in_sizes, int n_in,
                              void* d_out, int out_size) {
    const void*  x_in  = d_in[0];
    const void*  xlen  = d_in[1];
    const float* emb   = (const float*)d_in[2];
    const float* W_ih  = (const float*)d_in[3];
    const float* b_ih  = (const float*)d_in[4];
    const float* W_hh  = (const float*)d_in[5];
    const float* b_hh  = (const float*)d_in[6];
    const float* W1    = (const float*)d_in[7];
    const float* b1    = (const float*)d_in[8];
    const float* W2    = (const float*)d_in[9];
    const float* b2    = (const float*)d_in[10];
    float* out = (float*)d_out;

    float *Tp, *lastp, *mlp1p;
    cudaGetSymbolAddress((void**)&Tp,    g_T);
    cudaGetSymbolAddress((void**)&lastp, g_last);
    cudaGetSymbolAddress((void**)&mlp1p, g_mlp1);

    cudaFuncSetAttribute(rnn_mma,
                         cudaFuncAttributeMaxDynamicSharedMemorySize, SMEM_BYTES);

    convert_inputs<<<(BB * SS + 255) / 256, 256>>>(x_in, xlen);
    split_whh<<<(HH * HH + 255) / 256, 256>>>(W_hh);

    // T[v][h] = emb[v]·W_ih[h] + b_ih[h] + b_hh[h]
    gemm_bias_act<<<dim3(HH / 64, VV / 32), 256>>>(emb, W_ih, b_ih, b_hh, Tp,
                                                   VV, HH, EE, 0);

    // Persistent tensor-core RNN over all 128 steps.
    rnn_mma<<<128, 256, SMEM_BYTES>>>();

    // MLP head.
    gemm_bias_act<<<dim3(HH / 64, BB / 32), 256>>>(lastp, W1, b1, nullptr, mlp1p,
                                                   BB, HH, HH, 1);
    gemm_bias_act<<<dim3(1, BB / 32), 256>>>(mlp1p, W2, b2, nullptr, out,
                                             BB, CC, HH, 0);
}

// round 13
// speedup vs baseline: 1.0124x; 1.0124x over previous
#include <cuda_runtime.h>
#include <cuda_bf16.h>
#include <math.h>
#include <stdint.h>

#define BB 256
#define SS 128
#define EE 512
#define HH 1024
#define VV 128
#define CC 18

// ---------------- device scratch (no cudaMalloc allowed) ----------------
__device__ float          g_T[VV * HH];     // T[v][h] = W_ih.emb[v] + b_ih + b_hh
__device__ __nv_bfloat16  g_ah[BB * HH];    // h split hi (bf16)
__device__ __nv_bfloat16  g_al[BB * HH];    // h split lo (bf16)
__device__ __nv_bfloat16  g_wh[HH * HH];    // W_hh split hi
__device__ __nv_bfloat16  g_wl[HH * HH];    // W_hh split lo
__device__ float          g_last[BB * HH];
__device__ float          g_mlp1[BB * HH];
__device__ int            g_xin[BB * SS];
__device__ int            g_len[BB];
__device__ int            g_cnt[4];
__device__ volatile int   g_sense[4];

// ---------------------------------------------------------------------------
// Preprocessing
// ---------------------------------------------------------------------------
__global__ void __launch_bounds__(256) convert_inputs(const void* xin_raw,
                                                      const void* xlen_raw) {
    long long probe = ((const long long*)xlen_raw)[0];
    bool is64 = (probe >= 1 && probe <= SS);
    int i = blockIdx.x * blockDim.x + threadIdx.x;
    if (i < BB * SS) {
        g_xin[i] = is64 ? (int)((const long long*)xin_raw)[i]
                        : ((const int*)xin_raw)[i];
    }
    if (i < BB) {
        g_len[i] = is64 ? (int)((const long long*)xlen_raw)[i]
                        : ((const int*)xlen_raw)[i];
    }
}

__global__ void __launch_bounds__(256) split_whh(const float* __restrict__ W) {
    int i = blockIdx.x * blockDim.x + threadIdx.x;
    if (i < HH * HH) {
        float w = W[i];
        __nv_bfloat16 hi = __float2bfloat16_rn(w);
        float lo = w - __bfloat162float(hi);
        g_wh[i] = hi;
        g_wl[i] = __float2bfloat16_rn(lo);
    }
}

// ---------------------------------------------------------------------------
// Generic tiled GEMM (aux)
// ---------------------------------------------------------------------------
__global__ void __launch_bounds__(256) gemm_bias_act(
    const float* __restrict__ A, const float* __restrict__ Bm,
    const float* __restrict__ bias, const float* __restrict__ bias2,
    float* __restrict__ Cout, int M, int N, int K, int act)
{
    __shared__ float As[32][33];
    __shared__ float Bs[32][65];

    const int tid = threadIdx.x;
    const int tx = tid & 15;
    const int ty = tid >> 4;
    const int m0 = blockIdx.y * 32;
    const int n0 = blockIdx.x * 64;
    const int ka = tid & 31;
    const int ra = tid >> 5;

    float acc[2][4] = {};

    for (int k0 = 0; k0 < K; k0 += 32) {
        #pragma unroll
        for (int r = 0; r < 4; r++)
            As[ka][ra + r * 8] = A[(size_t)(m0 + ra + r * 8) * K + k0 + ka];
        #pragma unroll
        for (int r = 0; r < 8; r++) {
            int n = ra + r * 8;
            float v = 0.0f;
            if (n0 + n < N) v = Bm[(size_t)(n0 + n) * K + k0 + ka];
            Bs[ka][n] = v;
        }
        __syncthreads();
        #pragma unroll
        for (int kk = 0; kk < 32; kk++) {
            float a[2], b[4];
            #pragma unroll
            for (int i = 0; i < 2; i++) a[i] = As[kk][ty * 2 + i];
            #pragma unroll
            for (int j = 0; j < 4; j++) b[j] = Bs[kk][tx * 4 + j];
            #pragma unroll
            for (int i = 0; i < 2; i++)
                #pragma unroll
                for (int j = 0; j < 4; j++)
                    acc[i][j] = fmaf(a[i], b[j], acc[i][j]);
        }
        __syncthreads();
    }

    #pragma unroll
    for (int i = 0; i < 2; i++) {
        int m = m0 + ty * 2 + i;
        if (m >= M) continue;
        #pragma unroll
        for (int j = 0; j < 4; j++) {
            int n = n0 + tx * 4 + j;
            if (n >= N) continue;
            float z = acc[i][j] + bias[n];
            if (bias2) z += bias2[n];
            if (act == 1) z = fmaxf(z, 0.0f);
            Cout[(size_t)m * N + n] = z;
        }
    }
}

// ---------------------------------------------------------------------------
// Persistent RNN on tensor cores via mma.sync m16n8k16 bf16 (3-term split).
// 128 CTAs = 4 m-groups (64 rows) x 32 n-blocks (32 cols), 256 threads.
// W_hh (hi+lo) resident in smem k-major [n][kpair-u32]; A streamed per step
// in 8 chunks of k=128 (double-buffered smem, register prefetch).
// Warps: 4 m x 2 n, warp tile m16 x n32 (two n8 tiles per 16-col span... 4 n8
// tiles total: cols 16*wn + {0,8} only => n16 per warp? No: wn in {0,1} covers
// cols 0..15 / 16..31 with 2 n8 tiles each).
// ---------------------------------------------------------------------------
#define WS 516                       // u32 stride per W row (512 + 4 pad)
#define AS 68                        // u32 stride per A row (64 + 4 pad)
#define WH_OFF 0
#define WL_OFF (32 * WS)             // 16512
#define AB_OFF (2 * 32 * WS)         // 33024
#define A_CH   (64 * AS)             // 4352 u32 per chunk
#define AB_STEP (2 * A_CH)           // hi+lo per buffer
#define SMEM_U32 (AB_OFF + 2 * AB_STEP)
#define SMEM_BYTES (SMEM_U32 * 4)    // 201728

#define MMA(c, A0, A1, A2, A3, B0, B1) \
    asm volatile( \
        "mma.sync.aligned.m16n8k16.row.col.f32.bf16.bf16.f32 " \
        "{%0,%1,%2,%3}, {%4,%5,%6,%7}, {%8,%9}, {%0,%1,%2,%3};" \
        : "+f"((c)[0]), "+f"((c)[1]), "+f"((c)[2]), "+f"((c)[3]) \
        : "r"(A0), "r"(A1), "r"(A2), "r"(A3), "r"(B0), "r"(B1))

__global__ void __launch_bounds__(256, 1) rnn_mma()
{
    extern __shared__ uint32_t sm[];

    const int tid = threadIdx.x;
    const int wid = tid >> 5;
    const int lid = tid & 31;
    const int gi = blockIdx.x >> 5;        // m-group 0..3
    const int gj = blockIdx.x & 31;        // n-block 0..31
    const int m0 = gi * 64;
    const int n0 = gj * 32;

    const int g = lid >> 2;                // 0..7
    const int q = lid & 3;                 // 0..3
    const int wm = wid & 3;                // m-warp 0..3
    const int wn = wid >> 2;               // n-warp 0..1
    const int mwl = 16 * wm;               // local row base
    const int nwl = 16 * wn;               // local col base

    // ---- load resident W (hi+lo) k-major into smem ----
    {
        const uint4* gwh = (const uint4*)g_wh;
        const uint4* gwl = (const uint4*)g_wl;
        for (int idx = tid; idx < 32 * 128; idx += 256) {
            int row = idx >> 7;            // 0..31
            int slot = idx & 127;          // uint4 slot (4 kpairs)
            uint4 vh = gwh[(size_t)(n0 + row) * 128 + slot];
            uint4 vl = gwl[(size_t)(n0 + row) * 128 + slot];
            *(uint4*)(sm + WH_OFF + row * WS + slot * 4) = vh;
            *(uint4*)(sm + WL_OFF + row * WS + slot * 4) = vl;
        }
    }
    __syncthreads();

    // per-lane W bases (u32 index)
    const int wb0h = WH_OFF + (nwl + g) * WS + q;       // n8-tile 0
    const int wb1h = wb0h + 8 * WS;                     // n8-tile 1
    const int wb0l = wb0h + (WL_OFF - WH_OFF);
    const int wb1l = wb1h + (WL_OFF - WH_OFF);
    // per-lane A frag bases (relative to chunk buffer)
    const int ar0 = (mwl + g) * AS + q;
    const int ar1 = ar0 + 8 * AS;

    // staging coords: row = (tid>>4)+16j, slot = tid&15 (uint4)
    const int st_r = tid >> 4;
    const int st_s = tid & 15;

    // epilogue row info
    const int me0 = m0 + mwl + g;
    const int me1 = me0 + 8;
    const int len0 = g_len[me0];
    const int len1 = g_len[me1];
    const int colb = n0 + nwl + 2 * q;     // tile0 col base (even)

    const uint4* gah = (const uint4*)g_ah;
    const uint4* gal = (const uint4*)g_al;

    for (int t = 0; t < SS; t++) {
        float acc0[4] = {0.f, 0.f, 0.f, 0.f};   // n8 tile 0
        float acc1[4] = {0.f, 0.f, 0.f, 0.f};   // n8 tile 1

        if (t > 0) {
            uint4 pfh[4], pfl[4];
            // prefetch + store chunk 0
            #pragma unroll
            for (int j = 0; j < 4; j++) {
                int row = st_r + 16 * j;
                size_t gidx = (size_t)(m0 + row) * 128 + st_s;
                pfh[j] = __ldcg(gah + gidx);
                pfl[j] = __ldcg(gal + gidx);
            }
            #pragma unroll
            for (int j = 0; j < 4; j++) {
                int row = st_r + 16 * j;
                *(uint4*)(sm + AB_OFF + row * AS + st_s * 4) = pfh[j];
                *(uint4*)(sm + AB_OFF + A_CH + row * AS + st_s * 4) = pfl[j];
            }
            __syncthreads();

            for (int c = 0; c < 8; c++) {
                // prefetch chunk c+1
                if (c + 1 < 8) {
                    #pragma unroll
                    for (int j = 0; j < 4; j++) {
                        int row = st_r + 16 * j;
                        size_t gidx = (size_t)(m0 + row) * 128 + (c + 1) * 16 + st_s;
                        pfh[j] = __ldcg(gah + gidx);
                        pfl[j] = __ldcg(gal + gidx);
                    }
                }

                // compute chunk c (8 k16-steps)
                const int ab = AB_OFF + (c & 1) * AB_STEP;
                #pragma unroll
                for (int ks = 0; ks < 8; ks++) {
                    const int ka = ks * 8;                // A kpair offset
                    const int kw = c * 64 + ks * 8;       // W kpair offset
                    uint32_t ah0 = sm[ab + ar0 + ka];
                    uint32_t ah1 = sm[ab + ar1 + ka];
                    uint32_t ah2 = sm[ab + ar0 + ka + 4];
                    uint32_t ah3 = sm[ab + ar1 + ka + 4];
                    uint32_t bh00 = sm[wb0h + kw];
                    uint32_t bh01 = sm[wb0h + kw + 4];
                    uint32_t bh10 = sm[wb1h + kw];
                    uint32_t bh11 = sm[wb1h + kw + 4];
                    MMA(acc0, ah0, ah1, ah2, ah3, bh00, bh01);
                    MMA(acc1, ah0, ah1, ah2, ah3, bh10, bh11);
                    uint32_t bl00 = sm[wb0l + kw];
                    uint32_t bl01 = sm[wb0l + kw + 4];
                    uint32_t bl10 = sm[wb1l + kw];
                    uint32_t bl11 = sm[wb1l + kw + 4];
                    MMA(acc0, ah0, ah1, ah2, ah3, bl00, bl01);
                    MMA(acc1, ah0, ah1, ah2, ah3, bl10, bl11);
                    uint32_t al0 = sm[ab + A_CH + ar0 + ka];
                    uint32_t al1 = sm[ab + A_CH + ar1 + ka];
                    uint32_t al2 = sm[ab + A_CH + ar0 + ka + 4];
                    uint32_t al3 = sm[ab + A_CH + ar1 + ka + 4];
                    MMA(acc0, al0, al1, al2, al3, bh00, bh01);
                    MMA(acc1, al0, al1, al2, al3, bh10, bh11);
                }

                // store prefetched chunk
                if (c + 1 < 8) {
                    const int db = AB_OFF + ((c + 1) & 1) * AB_STEP;
                    #pragma unroll
                    for (int j = 0; j < 4; j++) {
                        int row = st_r + 16 * j;
                        *(uint4*)(sm + db + row * AS + st_s * 4) = pfh[j];
                        *(uint4*)(sm + db + A_CH + row * AS + st_s * 4) = pfl[j];
                    }
                }
                __syncthreads();
            }
        }

        // ---- epilogue: 2 rows x 4 cols per thread ----
        #pragma unroll
        for (int r = 0; r < 2; r++) {
            int m = r ? me1 : me0;
            int xi = g_xin[m * SS + t];
            float2 tv0 = *(const float2*)(g_T + (size_t)xi * HH + colb);
            float2 tv1 = *(const float2*)(g_T + (size_t)xi * HH + colb + 8);
            float v0 = tv0.x, v1 = tv0.y, v2 = tv1.x, v3 = tv1.y;
            if (t > 0) {
                v0 += acc0[2 * r];  v1 += acc0[2 * r + 1];
                v2 += acc1[2 * r];  v3 += acc1[2 * r + 1];
            }
            v0 = tanhf(v0); v1 = tanhf(v1); v2 = tanhf(v2); v3 = tanhf(v3);

            __nv_bfloat16 h0 = __float2bfloat16_rn(v0);
            __nv_bfloat16 h1 = __float2bfloat16_rn(v1);
            __nv_bfloat16 h2 = __float2bfloat16_rn(v2);
            __nv_bfloat16 h3 = __float2bfloat16_rn(v3);
            __nv_bfloat16 l0 = __float2bfloat16_rn(v0 - __bfloat162float(h0));
            __nv_bfloat16 l1 = __float2bfloat16_rn(v1 - __bfloat162float(h1));
            __nv_bfloat16 l2 = __float2bfloat16_rn(v2 - __bfloat162float(h2));
            __nv_bfloat16 l3 = __float2bfloat16_rn(v3 - __bfloat162float(h3));

            uint32_t* ph = (uint32_t*)g_ah + (size_t)m * (HH / 2) + colb / 2;
            uint32_t* pl = (uint32_t*)g_al + (size_t)m * (HH / 2) + colb / 2;
            ph[0] = (uint32_t)__bfloat16_as_ushort(h0)
                  | ((uint32_t)__bfloat16_as_ushort(h1) << 16);
            ph[4] = (uint32_t)__bfloat16_as_ushort(h2)
                  | ((uint32_t)__bfloat16_as_ushort(h3) << 16);
            pl[0] = (uint32_t)__bfloat16_as_ushort(l0)
                  | ((uint32_t)__bfloat16_as_ushort(l1) << 16);
            pl[4] = (uint32_t)__bfloat16_as_ushort(l2)
                  | ((uint32_t)__bfloat16_as_ushort(l3) << 16);

            if (t == (r ? len1 : len0) - 1) {
                float2* dl = (float2*)(g_last + (size_t)m * HH + colb);
                dl[0] = make_float2(v0, v1);
                dl[4] = make_float2(v2, v3);
            }
        }

        // ---- per-m-group barrier (32 CTAs), replay-safe ----
        __syncthreads();
        if (tid == 0) {
            __threadfence();
            int target = (t + 1) & 127;
            int arrived = atomicAdd(&g_cnt[gi], 1);
            if (arrived == 31) {
                g_cnt[gi] = 0;
                __threadfence();
                g_sense[gi] = target;
            } else {
                while (g_sense[gi] != target) { }
                __threadfence();
            }
        }
        __syncthreads();
    }
}

extern "C" void kernel_launch(void* const* d_in, const int* in_sizes, int n_in,
                              void* d_out, int out_size) {
    const void*  x_in  = d_in[0];
    const void*  xlen  = d_in[1];
    const float* emb   = (const float*)d_in[2];
    const float* W_ih  = (const float*)d_in[3];
    const float* b_ih  = (const float*)d_in[4];
    const float* W_hh  = (const float*)d_in[5];
    const float* b_hh  = (const float*)d_in[6];
    const float* W1    = (const float*)d_in[7];
    const float* b1    = (const float*)d_in[8];
    const float* W2    = (const float*)d_in[9];
    const float* b2    = (const float*)d_in[10];
    float* out = (float*)d_out;

    float *Tp, *lastp, *mlp1p;
    cudaGetSymbolAddress((void**)&Tp,    g_T);
    cudaGetSymbolAddress((void**)&lastp, g_last);
    cudaGetSymbolAddress((void**)&mlp1p, g_mlp1);

    cudaFuncSetAttribute(rnn_mma,
                         cudaFuncAttributeMaxDynamicSharedMemorySize, SMEM_BYTES);

    convert_inputs<<<(BB * SS + 255) / 256, 256>>>(x_in, xlen);
    split_whh<<<(HH * HH + 255) / 256, 256>>>(W_hh);

    // T[v][h] = emb[v]·W_ih[h] + b_ih[h] + b_hh[h]
    gemm_bias_act<<<dim3(HH / 64, VV / 32), 256>>>(emb, W_ih, b_ih, b_hh, Tp,
                                                   VV, HH, EE, 0);

    // Persistent tensor-core RNN over all 128 steps.
    rnn_mma<<<128, 256, SMEM_BYTES>>>();

    // MLP head.
    gemm_bias_act<<<dim3(HH / 64, BB / 32), 256>>>(lastp, W1, b1, nullptr, mlp1p,
                                                   BB, HH, HH, 1);
    gemm_bias_act<<<dim3(1, BB / 32), 256>>>(mlp1p, W2, b2, nullptr, out,
                                             BB, CC, HH, 0);
}